// round 3
// baseline (speedup 1.0000x reference)
#include <cuda_runtime.h>
#include <cstdint>

#define B 8
#define DIM 192
#define Hh 128
#define Ww 128
#define KS 7
#define PAD 3
#define HID 48
#define KK 49          // 7*7
#define PLANE (Hh*Ww)  // 16384
#define OUTW (DIM*KK)  // 9408
#define EPS 1e-5f

// -------- scratch (device globals; no allocation allowed) --------
__device__ float g_pooled[B * DIM];      // [b, c]
__device__ float g_y[B * HID];           // [b, h]
__device__ float g_wdyn[B * OUTW];       // [b, c*49 + k]

// -------- f32x2 packed helpers (Blackwell) --------
__device__ __forceinline__ unsigned long long ffma2(
    unsigned long long a, unsigned long long b, unsigned long long c) {
    unsigned long long d;
    asm("fma.rn.f32x2 %0, %1, %2, %3;" : "=l"(d) : "l"(a), "l"(b), "l"(c));
    return d;
}
__device__ __forceinline__ unsigned long long pk2(float lo, float hi) {
    unsigned long long r;
    asm("mov.b64 %0, {%1, %2};" : "=l"(r) : "f"(lo), "f"(hi));
    return r;
}
__device__ __forceinline__ void unpk2(unsigned long long v, float& lo, float& hi) {
    asm("mov.b64 {%0, %1}, %2;" : "=f"(lo), "=f"(hi) : "l"(v));
}

// ============================================================
// Kernel 1: global average pool over HxW per (b,c) plane
// ============================================================
__global__ __launch_bounds__(256) void pool_kernel(const float* __restrict__ x) {
    int bc = blockIdx.x;
    const float4* p = reinterpret_cast<const float4*>(x + (size_t)bc * PLANE);
    float s = 0.f;
    #pragma unroll 4
    for (int i = threadIdx.x; i < PLANE / 4; i += 256) {
        float4 v = p[i];
        s += (v.x + v.y) + (v.z + v.w);
    }
    #pragma unroll
    for (int off = 16; off > 0; off >>= 1)
        s += __shfl_down_sync(0xffffffffu, s, off);
    __shared__ float red[8];
    int lane = threadIdx.x & 31, warp = threadIdx.x >> 5;
    if (lane == 0) red[warp] = s;
    __syncthreads();
    if (warp == 0) {
        float t = (lane < 8) ? red[lane] : 0.f;
        #pragma unroll
        for (int off = 4; off > 0; off >>= 1)
            t += __shfl_down_sync(0xffffffffu, t, off);
        if (lane == 0) g_pooled[bc] = t * (1.0f / (float)PLANE);
    }
}

// ============================================================
// Kernel 2a: y = relu(BN(pooled @ w1^T))   [b, HID]
// ============================================================
__global__ __launch_bounds__(64) void gen_y_kernel(
    const float* __restrict__ w1,
    const float* __restrict__ gamma, const float* __restrict__ beta,
    const float* __restrict__ mean,  const float* __restrict__ var) {
    int b = blockIdx.x;
    int t = threadIdx.x;
    if (t >= HID) return;
    const float* pr = g_pooled + b * DIM;
    const float* wr = w1 + t * DIM;
    float s = 0.f;
    #pragma unroll 8
    for (int c = 0; c < DIM; c++) s = fmaf(pr[c], wr[c], s);
    s = (s - mean[t]) * rsqrtf(var[t] + EPS) * gamma[t] + beta[t];
    g_y[b * HID + t] = s > 0.f ? s : 0.f;
}

// ============================================================
// Kernel 2b: wdyn[b, o] = y[b,:] . w2[o,:] + b2[o]
// ============================================================
#define W2_CHUNK 128
__global__ __launch_bounds__(128) void gen_wdyn_kernel(
    const float* __restrict__ w2, const float* __restrict__ b2) {
    int b = blockIdx.y;
    int obase = blockIdx.x * W2_CHUNK;
    int t = threadIdx.x;

    __shared__ float sy[HID];
    __shared__ float w2s[W2_CHUNK * (HID + 1)];

    if (t < HID) sy[t] = g_y[b * HID + t];

    const int n_f4 = W2_CHUNK * HID / 4;
    const float4* w2v = reinterpret_cast<const float4*>(w2 + (size_t)obase * HID);
    int max_f4 = (OUTW - obase) * HID / 4;
    for (int i = t; i < n_f4; i += 128) {
        float4 v = (i < max_f4) ? w2v[i] : make_float4(0.f, 0.f, 0.f, 0.f);
        int row = i / (HID / 4);
        int col = (i % (HID / 4)) * 4;
        float* dst = &w2s[row * (HID + 1) + col];
        dst[0] = v.x; dst[1] = v.y; dst[2] = v.z; dst[3] = v.w;
    }
    __syncthreads();

    int o = obase + t;
    if (o < OUTW) {
        float acc = b2[o];
        const float* wr = &w2s[t * (HID + 1)];
        #pragma unroll
        for (int h = 0; h < HID; h++) acc = fmaf(sy[h], wr[h], acc);
        g_wdyn[(size_t)b * OUTW + o] = acc;
    }
}

// ============================================================
// Kernel 3: per-sample depthwise 7x7 conv + bias, f32x2 packed
// across a CHANNEL PAIR (planes 2p, 2p+1 share spatial coords).
// block = 128 threads = 128 cols; covers 2 planes x 8 output rows.
// grid = (B*DIM/2, 128/8) = (768, 16).
// smem tile: channel-interleaved float2 [14][136]; one LDS.64 per
// (row,col) yields both channels; kw shifts are whole-float2 steps
// so no pair reconstruction is ever needed.
// 98 packed weights live in registers (196 scalar weights -> 98 regs).
// ============================================================
#define RPT2 8
#define TR2 (RPT2 + KS - 1)   // 14
#define TC2 (Ww + KS - 1)     // 134
#define TS2 136               // padded float2 stride

__global__ __launch_bounds__(128, 3) void dwconv2_kernel(
    const float* __restrict__ x, const float* __restrict__ bias,
    float* __restrict__ out) {
    int pp = blockIdx.x;           // plane-pair index: planes 2pp, 2pp+1
    int strip = blockIdx.y;
    int pc = pp * 2;               // global plane index (b*DIM + c), even
    int c0 = pc % DIM;             // channel of plane 0 (c0+1 = plane 1, same b)
    int r0 = strip * RPT2;

    __shared__ float2 tile[TR2 * TS2];
    __shared__ float wsm[2 * KK];

    int tid = threadIdx.x;

    // stage both channels' dynamic weights (contiguous: pc*49 .. pc*49+97)
    if (tid < 2 * KK) wsm[tid] = g_wdyn[(size_t)pc * KK + tid];

    // build channel-interleaved halo tile
    const float* p0 = x + (size_t)pc * PLANE;
    const float* p1 = p0 + PLANE;
    for (int idx = tid; idx < TR2 * TC2; idx += 128) {
        int rr = idx / TC2, cc = idx % TC2;
        int gr = r0 + rr - PAD, gc = cc - PAD;
        float v0 = 0.f, v1 = 0.f;
        if (gr >= 0 && gr < Hh && gc >= 0 && gc < Ww) {
            int o = gr * Ww + gc;
            v0 = p0[o]; v1 = p1[o];
        }
        tile[rr * TS2 + cc] = make_float2(v0, v1);
    }
    __syncthreads();

    // pack weights into registers: w[k] = {w_c0[k], w_c1[k]}
    unsigned long long w[KK];
    #pragma unroll
    for (int k = 0; k < KK; k++) w[k] = pk2(wsm[k], wsm[KK + k]);

    int col = tid;
    unsigned long long binit = pk2(bias[c0], bias[c0 + 1]);
    unsigned long long acc[RPT2];
    #pragma unroll
    for (int i = 0; i < RPT2; i++) acc[i] = binit;

    const unsigned long long* tl =
        reinterpret_cast<const unsigned long long*>(tile);

    #pragma unroll
    for (int ir = 0; ir < TR2; ir++) {
        unsigned long long vv[KS];
        const unsigned long long* trow = tl + ir * TS2 + col;
        #pragma unroll
        for (int kw = 0; kw < KS; kw++) vv[kw] = trow[kw];
        #pragma unroll
        for (int kh = 0; kh < KS; kh++) {
            int orr = ir - kh;
            if (orr >= 0 && orr < RPT2) {
                unsigned long long a = acc[orr];
                #pragma unroll
                for (int kw = 0; kw < KS; kw++)
                    a = ffma2(vv[kw], w[kh * KS + kw], a);
                acc[orr] = a;
            }
        }
    }

    float* o0 = out + (size_t)pc * PLANE + (size_t)r0 * Ww + col;
    #pragma unroll
    for (int i = 0; i < RPT2; i++) {
        float lo, hi;
        unpk2(acc[i], lo, hi);
        o0[(size_t)i * Ww] = lo;            // channel c0 plane
        o0[PLANE + (size_t)i * Ww] = hi;    // channel c0+1 plane
    }
}

// ============================================================
// launch
// inputs: 0:x 1:w1 2:bn_gamma 3:bn_beta 4:bn_mean 5:bn_var 6:w2 7:b2 8:bias
// ============================================================
extern "C" void kernel_launch(void* const* d_in, const int* in_sizes, int n_in,
                              void* d_out, int out_size) {
    const float* x     = (const float*)d_in[0];
    const float* w1    = (const float*)d_in[1];
    const float* gamma = (const float*)d_in[2];
    const float* beta  = (const float*)d_in[3];
    const float* mean  = (const float*)d_in[4];
    const float* var   = (const float*)d_in[5];
    const float* w2    = (const float*)d_in[6];
    const float* b2    = (const float*)d_in[7];
    const float* bias  = (const float*)d_in[8];
    float* out = (float*)d_out;

    pool_kernel<<<B * DIM, 256>>>(x);
    gen_y_kernel<<<B, 64>>>(w1, gamma, beta, mean, var);
    dim3 g2((OUTW + W2_CHUNK - 1) / W2_CHUNK, B);
    gen_wdyn_kernel<<<g2, 128>>>(w2, b2);
    dim3 g3(B * DIM / 2, Hh / RPT2);
    dwconv2_kernel<<<g3, 128>>>(x, bias, out);
}

// round 4
// speedup vs baseline: 2.5180x; 2.5180x over previous
#include <cuda_runtime.h>
#include <cstdint>

#define B 8
#define DIM 192
#define Hh 128
#define Ww 128
#define KS 7
#define PAD 3
#define HID 48
#define KK 49          // 7*7
#define PLANE (Hh*Ww)  // 16384
#define OUTW (DIM*KK)  // 9408
#define EPS 1e-5f

// -------- scratch (device globals; no allocation allowed) --------
__device__ float g_pooled[B * DIM];      // [b, c]
__device__ float g_wdyn[B * OUTW];       // [b, c*49 + k]

// ============================================================
// Kernel 1: global average pool over HxW per (b,c) plane
// grid = B*DIM, 256 threads
// ============================================================
__global__ __launch_bounds__(256) void pool_kernel(const float* __restrict__ x) {
    int bc = blockIdx.x;
    const float4* p = reinterpret_cast<const float4*>(x + (size_t)bc * PLANE);
    float s = 0.f;
    #pragma unroll 4
    for (int i = threadIdx.x; i < PLANE / 4; i += 256) {
        float4 v = p[i];
        s += (v.x + v.y) + (v.z + v.w);
    }
    #pragma unroll
    for (int off = 16; off > 0; off >>= 1)
        s += __shfl_down_sync(0xffffffffu, s, off);
    __shared__ float red[8];
    int lane = threadIdx.x & 31, warp = threadIdx.x >> 5;
    if (lane == 0) red[warp] = s;
    __syncthreads();
    if (warp == 0) {
        float t = (lane < 8) ? red[lane] : 0.f;
        #pragma unroll
        for (int off = 4; off > 0; off >>= 1)
            t += __shfl_down_sync(0xffffffffu, t, off);
        if (lane == 0) g_pooled[bc] = t * (1.0f / (float)PLANE);
    }
}

// ============================================================
// Kernel 2 (fused): y = relu(BN(pooled @ w1^T)) recomputed per block,
// then wdyn[b, o] = y . w2[o,:] + b2[o] for a 128-wide chunk of o.
// grid = (74, B), 128 threads.
// ============================================================
#define W2_CHUNK 128
__global__ __launch_bounds__(128) void gen_wdyn_kernel(
    const float* __restrict__ w1,
    const float* __restrict__ gamma, const float* __restrict__ beta,
    const float* __restrict__ mean,  const float* __restrict__ var,
    const float* __restrict__ w2, const float* __restrict__ b2) {
    int b = blockIdx.y;
    int obase = blockIdx.x * W2_CHUNK;
    int t = threadIdx.x;

    __shared__ float sy[HID];
    __shared__ float w2s[W2_CHUNK * (HID + 1)];

    // recompute y[b, t] for t < 48 (tiny: 192-FMA dot + BN + ReLU)
    if (t < HID) {
        const float* pr = g_pooled + b * DIM;
        const float* wr = w1 + t * DIM;
        float s = 0.f;
        #pragma unroll 8
        for (int c = 0; c < DIM; c++) s = fmaf(pr[c], wr[c], s);
        s = (s - mean[t]) * rsqrtf(var[t] + EPS) * gamma[t] + beta[t];
        sy[t] = s > 0.f ? s : 0.f;
    }

    // coalesced staged load of w2 rows [obase, obase+128)
    const int n_f4 = W2_CHUNK * HID / 4;          // 1536 float4
    const float4* w2v = reinterpret_cast<const float4*>(w2 + (size_t)obase * HID);
    int max_f4 = (OUTW - obase) * HID / 4;
    for (int i = t; i < n_f4; i += 128) {
        float4 v = (i < max_f4) ? w2v[i] : make_float4(0.f, 0.f, 0.f, 0.f);
        int row = i / (HID / 4);
        int col = (i % (HID / 4)) * 4;
        float* dst = &w2s[row * (HID + 1) + col];
        dst[0] = v.x; dst[1] = v.y; dst[2] = v.z; dst[3] = v.w;
    }
    __syncthreads();

    int o = obase + t;
    if (o < OUTW) {
        float acc = b2[o];
        const float* wr = &w2s[t * (HID + 1)];
        #pragma unroll
        for (int h = 0; h < HID; h++) acc = fmaf(sy[h], wr[h], acc);
        g_wdyn[(size_t)b * OUTW + o] = acc;
    }
}

// ============================================================
// Kernel 3: per-sample depthwise 7x7 conv + bias.
// grid = (B*DIM, 4): one plane x one 32-row strip.
// 256 threads = 32 col-groups x 8 row-groups; each thread computes
// a 4x4 output patch. Weights (49) live in registers
// (launch_bounds(256,2) gives the 128-reg budget to keep them there).
// Per tile row: LDS.128 + LDS.128 + LDS.64 (10-float window), then
// up to 4 valid kh x 4 cols x 7 kw FFMAs. 784 FFMA / 30 LDS per thread.
// ============================================================
#define STRIP 32
#define TROWS (STRIP + KS - 1)   // 38
#define TCOLS (Ww + KS - 1)      // 134
#define TSTRIDE 136              // 544 B row stride: keeps 16B alignment

__global__ __launch_bounds__(256, 2) void dwconv_kernel(
    const float* __restrict__ x, const float* __restrict__ bias,
    float* __restrict__ out) {
    int bc = blockIdx.x;             // b*DIM + c
    int strip = blockIdx.y;
    int r0 = strip * STRIP;

    __shared__ __align__(16) float tile[TROWS * TSTRIDE];
    __shared__ float wsh[KK];

    int tid = threadIdx.x;
    if (tid < KK) wsh[tid] = g_wdyn[(size_t)bc * KK + tid];

    // tile load: warp w handles rows w, w+8, ...; lanes stride cols
    const float* plane = x + (size_t)bc * PLANE;
    int warp = tid >> 5, lane = tid & 31;
    for (int rr = warp; rr < TROWS; rr += 8) {
        int gr = r0 + rr - PAD;
        bool rok = (gr >= 0) && (gr < Hh);
        const float* rp = plane + (size_t)gr * Ww;
        #pragma unroll
        for (int cc = lane; cc < TCOLS; cc += 32) {
            int gc = cc - PAD;
            float v = 0.f;
            if (rok && gc >= 0 && gc < Ww) v = __ldg(rp + gc);
            tile[rr * TSTRIDE + cc] = v;
        }
    }
    __syncthreads();

    // weights to registers
    float w[KK];
    #pragma unroll
    for (int k = 0; k < KK; k++) w[k] = wsh[k];

    int cg = tid & 31;               // col group (4 cols)
    int rg = tid >> 5;               // row group (4 rows)
    int col = cg * 4;
    int rbase = rg * 4;

    float bia = bias[bc % DIM];
    float acc[4][4];
    #pragma unroll
    for (int i = 0; i < 4; i++)
        #pragma unroll
        for (int j = 0; j < 4; j++) acc[i][j] = bia;

    #pragma unroll
    for (int ir = 0; ir < 4 + KS - 1; ir++) {     // 10 tile rows
        const float* tr = &tile[(rbase + ir) * TSTRIDE + col];
        float4 va = *reinterpret_cast<const float4*>(tr);
        float4 vb = *reinterpret_cast<const float4*>(tr + 4);
        float2 vc = *reinterpret_cast<const float2*>(tr + 8);
        float v[10] = {va.x, va.y, va.z, va.w, vb.x, vb.y, vb.z, vb.w, vc.x, vc.y};
        #pragma unroll
        for (int kh = 0; kh < KS; kh++) {
            int orr = ir - kh;
            if (orr >= 0 && orr < 4) {
                #pragma unroll
                for (int j = 0; j < 4; j++) {
                    float s = acc[orr][j];
                    #pragma unroll
                    for (int kw = 0; kw < KS; kw++)
                        s = fmaf(v[j + kw], w[kh * KS + kw], s);
                    acc[orr][j] = s;
                }
            }
        }
    }

    float* op = out + (size_t)bc * PLANE + (size_t)(r0 + rbase) * Ww + col;
    #pragma unroll
    for (int orr = 0; orr < 4; orr++)
        *reinterpret_cast<float4*>(op + (size_t)orr * Ww) =
            make_float4(acc[orr][0], acc[orr][1], acc[orr][2], acc[orr][3]);
}

// ============================================================
// launch
// inputs: 0:x 1:w1 2:bn_gamma 3:bn_beta 4:bn_mean 5:bn_var 6:w2 7:b2 8:bias
// ============================================================
extern "C" void kernel_launch(void* const* d_in, const int* in_sizes, int n_in,
                              void* d_out, int out_size) {
    const float* x     = (const float*)d_in[0];
    const float* w1    = (const float*)d_in[1];
    const float* gamma = (const float*)d_in[2];
    const float* beta  = (const float*)d_in[3];
    const float* mean  = (const float*)d_in[4];
    const float* var   = (const float*)d_in[5];
    const float* w2    = (const float*)d_in[6];
    const float* b2    = (const float*)d_in[7];
    const float* bias  = (const float*)d_in[8];
    float* out = (float*)d_out;

    pool_kernel<<<B * DIM, 256>>>(x);
    dim3 g2((OUTW + W2_CHUNK - 1) / W2_CHUNK, B);
    gen_wdyn_kernel<<<g2, 128>>>(w1, gamma, beta, mean, var, w2, b2);
    dim3 g3(B * DIM, Hh / STRIP);
    dwconv_kernel<<<g3, 256>>>(x, bias, out);
}